// round 7
// baseline (speedup 1.0000x reference)
#include <cuda_runtime.h>
#include <math.h>

#define NG   5000
#define IMH  512
#define IMW  512
#define HW   (IMH * IMW)
#define TPB  256
#define WPB  (TPB / 32)
#define ALPHA_T (1.0f / 255.0f)

// Accumulation scratch — zero-initialized at module load; phase 2 re-zeroes it
// every call, so "scratch == 0 on entry" is an invariant of kernel_launch.
__device__ float g_scratch[3 * HW];

// Sense-reversing grid barrier state (re-entrant across graph replays).
__device__ unsigned          g_cnt   = 0;
__device__ volatile unsigned g_sense = 0;

__device__ __forceinline__ void grid_barrier(int nblk) {
    __syncthreads();
    if (threadIdx.x == 0) {
        const unsigned my = g_sense;
        __threadfence();                       // publish this block's atomics
        const unsigned old = atomicAdd(&g_cnt, 1u);
        if (old == (unsigned)nblk - 1u) {
            g_cnt = 0;
            __threadfence();
            g_sense = my + 1u;                 // release
        } else {
            while (g_sense == my) { __nanosleep(64); }
        }
        __threadfence();                       // acquire
    }
    __syncthreads();
}

__global__ void __launch_bounds__(TPB, 4)      // regs<=64 -> 4 blocks/SM resident
fused_kernel(const float* __restrict__ xyz,
             const float* __restrict__ scaling,
             const float* __restrict__ rot,
             const float* __restrict__ feat,
             const float* __restrict__ opac,
             float* __restrict__ out,
             int nblk) {
    const int lane  = threadIdx.x & 31;
    const int warp  = blockIdx.x * WPB + (threadIdx.x >> 5);
    const int nwarp = nblk * WPB;

    // ---------------- phase 1: splat gaussians into g_scratch ----------------
    for (int g = warp; g < NG; g += nwarp) {
        const float mx = tanhf(xyz[2 * g + 0]);
        const float my = tanhf(xyz[2 * g + 1]);
        const float sx = fabsf(scaling[2 * g + 0] + 0.5f);
        const float sy = fabsf(scaling[2 * g + 1] + 0.5f);
        const float theta = (1.0f / (1.0f + expf(-rot[g]))) * 6.283185307179586f;

        const float cx = 0.5f * ((mx + 1.0f) * (float)IMW - 1.0f);
        const float cy = 0.5f * ((my + 1.0f) * (float)IMH - 1.0f);

        float sth, cth;
        sincosf(theta, &sth, &cth);
        const float sx2 = sx * sx;
        const float sy2 = sy * sy;
        const float a = cth * cth * sx2 + sth * sth * sy2;   // Sigma_xx
        const float b = cth * sth * (sx2 - sy2);             // Sigma_xy
        const float c = sth * sth * sx2 + cth * cth * sy2;   // Sigma_yy
        const float det = a * c - b * b;
        if (!(det > 0.0f)) continue;
        const float inv_det = 1.0f / fmaxf(det, 1e-12f);
        const float A =  c * inv_det;
        const float B = -b * inv_det;
        const float C =  a * inv_det;

        const float op = opac[g];
        if (!(op > ALPHA_T)) continue;
        const float smax = logf(255.0f * op);   // alpha>1/255 <=> sigma<smax
        if (!(smax > 0.0f)) continue;

        // exact AABB of the iso-ellipse sigma == smax
        const float dxm = sqrtf(2.0f * smax * a);
        const float dym = sqrtf(2.0f * smax * c);

        const int x0 = max(0,       (int)ceilf (cx - dxm));
        const int x1 = min(IMW - 1, (int)floorf(cx + dxm));
        const int y0 = max(0,       (int)ceilf (cy - dym));
        const int y1 = min(IMH - 1, (int)floorf(cy + dym));
        if (x0 > x1 || y0 > y1) continue;

        const int w    = x1 - x0 + 1;
        const int npix = w * (y1 - y0 + 1);

        const float cr = feat[3 * g + 0];
        const float cg = feat[3 * g + 1];
        const float cb = feat[3 * g + 2];

        for (int i = lane; i < npix; i += 32) {
            const int px = x0 + (i % w);
            const int py = y0 + (i / w);
            const float dx = cx - (float)px;
            const float dy = cy - (float)py;
            const float sigma = 0.5f * (A * dx * dx + C * dy * dy) + B * dx * dy;
            if (sigma >= 0.0f && sigma < smax) {          // cheap pre-test: no exp otherwise
                const float alpha = op * __expf(-sigma);
                if (alpha > ALPHA_T) {
                    const int p = py * IMW + px;
                    atomicAdd(&g_scratch[p],          alpha * cr);
                    atomicAdd(&g_scratch[HW + p],     alpha * cg);
                    atomicAdd(&g_scratch[2 * HW + p], alpha * cb);
                }
            }
        }
    }

    grid_barrier(nblk);

    // -------- phase 2: clamp -> d_out, and re-zero scratch for next call ------
    float4* __restrict__ s4 = reinterpret_cast<float4*>(g_scratch);
    float4* __restrict__ o4 = reinterpret_cast<float4*>(out);
    const int n4   = (3 * HW) / 4;
    const int nthr = nblk * TPB;
    const float4 z = make_float4(0.f, 0.f, 0.f, 0.f);
    for (int i = blockIdx.x * TPB + threadIdx.x; i < n4; i += nthr) {
        float4 v = __ldcg(s4 + i);                 // L2 read (skip L1)
        v.x = fminf(fmaxf(v.x, 0.f), 1.f);
        v.y = fminf(fmaxf(v.y, 0.f), 1.f);
        v.z = fminf(fmaxf(v.z, 0.f), 1.f);
        v.w = fminf(fmaxf(v.w, 0.f), 1.f);
        o4[i] = v;
        s4[i] = z;                                  // restore zero invariant
    }
}

// ---------------------------------------------------------------------------
// Inputs (metadata order): _xyz(N,2) _scaling(N,2) _rotation(N,1)
//                          _features_dc(N,3) _opacity(N,1)
// Output: float32 (1,3,512,512)
// ---------------------------------------------------------------------------
extern "C" void kernel_launch(void* const* d_in, const int* in_sizes, int n_in,
                              void* d_out, int out_size) {
    const float* xyz     = (const float*)d_in[0];
    const float* scaling = (const float*)d_in[1];
    const float* rot     = (const float*)d_in[2];
    const float* feat    = (const float*)d_in[3];
    const float* opac    = (const float*)d_in[4];
    float* out = (float*)d_out;

    int dev = 0, sms = 148;
    cudaGetDevice(&dev);
    cudaDeviceGetAttribute(&sms, cudaDevAttrMultiProcessorCount, dev);
    const int nblk = sms * 4;                      // guaranteed co-resident

    fused_kernel<<<nblk, TPB>>>(xyz, scaling, rot, feat, opac, out, nblk);
}

// round 8
// speedup vs baseline: 1.0201x; 1.0201x over previous
#include <cuda_runtime.h>
#include <math.h>

#define NG   5000
#define IMH  512
#define IMW  512
#define HW   (IMH * IMW)
#define TPB  512
#define WPB  (TPB / 32)
#define ALPHA_T (1.0f / 255.0f)

// Accumulation scratch — zero-initialized at module load; phase 2 re-zeroes it
// every call, so "scratch == 0 on entry" is an invariant of kernel_launch.
__device__ float g_scratch[3 * HW];

// Sense-reversing grid barrier state (re-entrant across graph replays).
__device__ unsigned          g_cnt   = 0;
__device__ volatile unsigned g_sense = 0;

__device__ __forceinline__ void grid_barrier(int nblk) {
    __syncthreads();
    if (threadIdx.x == 0) {
        const unsigned my = g_sense;
        __threadfence();                       // publish this block's RED atomics
        const unsigned old = atomicAdd(&g_cnt, 1u);
        if (old == (unsigned)nblk - 1u) {
            g_cnt = 0;
            atomicExch((unsigned*)&g_sense, my + 1u);   // release
        } else {
            while (g_sense == my) { __nanosleep(32); }
        }
    }
    __syncthreads();
}

// fast tanh via __expf: tanh(x) = sgn(x) * (1 - 2/(1 + e^{2|x|}))
__device__ __forceinline__ float fast_tanh(float x) {
    const float ax = fabsf(x);
    const float e  = __expf(2.0f * ax);
    const float t  = 1.0f - 2.0f / (1.0f + e);
    return copysignf(t, x);
}

__global__ void __launch_bounds__(TPB, 2)      // 2 blocks/SM co-resident
fused_kernel(const float* __restrict__ xyz,
             const float* __restrict__ scaling,
             const float* __restrict__ rot,
             const float* __restrict__ feat,
             const float* __restrict__ opac,
             float* __restrict__ out,
             int nblk) {
    const int lane  = threadIdx.x & 31;
    const int warp  = blockIdx.x * WPB + (threadIdx.x >> 5);
    const int nwarp = nblk * WPB;

    // ---------------- phase 1: splat gaussians into g_scratch ----------------
    for (int g = warp; g < NG; g += nwarp) {
        const float mx = fast_tanh(__ldg(&xyz[2 * g + 0]));
        const float my = fast_tanh(__ldg(&xyz[2 * g + 1]));
        const float sx = fabsf(__ldg(&scaling[2 * g + 0]) + 0.5f);
        const float sy = fabsf(__ldg(&scaling[2 * g + 1]) + 0.5f);
        const float theta = (1.0f / (1.0f + __expf(-__ldg(&rot[g]))))
                            * 6.283185307179586f;

        const float cx = 0.5f * ((mx + 1.0f) * (float)IMW - 1.0f);
        const float cy = 0.5f * ((my + 1.0f) * (float)IMH - 1.0f);

        const float sth = __sinf(theta);
        const float cth = __cosf(theta);
        const float sx2 = sx * sx;
        const float sy2 = sy * sy;
        const float a = cth * cth * sx2 + sth * sth * sy2;   // Sigma_xx
        const float b = cth * sth * (sx2 - sy2);             // Sigma_xy
        const float c = sth * sth * sx2 + cth * cth * sy2;   // Sigma_yy
        const float det = a * c - b * b;
        if (!(det > 0.0f)) continue;
        const float inv_det = 1.0f / fmaxf(det, 1e-12f);
        const float A =  c * inv_det;
        const float B = -b * inv_det;
        const float C =  a * inv_det;

        const float op = __ldg(&opac[g]);
        if (!(op > ALPHA_T)) continue;
        const float smax = __logf(255.0f * op);  // alpha>1/255 <=> sigma<smax
        if (!(smax > 0.0f)) continue;

        // exact AABB of the iso-ellipse sigma == smax
        const float dxm = sqrtf(2.0f * smax * a);
        const float dym = sqrtf(2.0f * smax * c);

        const int x0 = max(0,       (int)ceilf (cx - dxm));
        const int x1 = min(IMW - 1, (int)floorf(cx + dxm));
        const int y0 = max(0,       (int)ceilf (cy - dym));
        const int y1 = min(IMH - 1, (int)floorf(cy + dym));
        if (x0 > x1 || y0 > y1) continue;

        const int w    = x1 - x0 + 1;
        const int npix = w * (y1 - y0 + 1);

        const float cr = __ldg(&feat[3 * g + 0]);
        const float cg = __ldg(&feat[3 * g + 1]);
        const float cb = __ldg(&feat[3 * g + 2]);

        for (int i = lane; i < npix; i += 32) {
            const int px = x0 + (i % w);
            const int py = y0 + (i / w);
            const float dx = cx - (float)px;
            const float dy = cy - (float)py;
            const float sigma = 0.5f * (A * dx * dx + C * dy * dy) + B * dx * dy;
            if (sigma >= 0.0f && sigma < smax) {       // cheap pre-test
                const float alpha = op * __expf(-sigma);
                if (alpha > ALPHA_T) {
                    const int p = py * IMW + px;
                    atomicAdd(&g_scratch[p],          alpha * cr);
                    atomicAdd(&g_scratch[HW + p],     alpha * cg);
                    atomicAdd(&g_scratch[2 * HW + p], alpha * cb);
                }
            }
        }
    }

    grid_barrier(nblk);

    // -------- phase 2: clamp -> d_out, and re-zero scratch for next call ------
    float4* __restrict__ s4 = reinterpret_cast<float4*>(g_scratch);
    float4* __restrict__ o4 = reinterpret_cast<float4*>(out);
    const int n4   = (3 * HW) / 4;
    const int nthr = nblk * TPB;
    const float4 z = make_float4(0.f, 0.f, 0.f, 0.f);
    for (int i = blockIdx.x * TPB + threadIdx.x; i < n4; i += nthr) {
        float4 v = __ldcg(s4 + i);                 // L2 read (skip L1)
        v.x = fminf(fmaxf(v.x, 0.f), 1.f);
        v.y = fminf(fmaxf(v.y, 0.f), 1.f);
        v.z = fminf(fmaxf(v.z, 0.f), 1.f);
        v.w = fminf(fmaxf(v.w, 0.f), 1.f);
        o4[i] = v;
        s4[i] = z;                                  // restore zero invariant
    }
}

// ---------------------------------------------------------------------------
// Inputs (metadata order): _xyz(N,2) _scaling(N,2) _rotation(N,1)
//                          _features_dc(N,3) _opacity(N,1)
// Output: float32 (1,3,512,512)
// ---------------------------------------------------------------------------
extern "C" void kernel_launch(void* const* d_in, const int* in_sizes, int n_in,
                              void* d_out, int out_size) {
    const float* xyz     = (const float*)d_in[0];
    const float* scaling = (const float*)d_in[1];
    const float* rot     = (const float*)d_in[2];
    const float* feat    = (const float*)d_in[3];
    const float* opac    = (const float*)d_in[4];
    float* out = (float*)d_out;

    int dev = 0, sms = 152;
    cudaGetDevice(&dev);
    cudaDeviceGetAttribute(&sms, cudaDevAttrMultiProcessorCount, dev);
    const int nblk = sms * 2;                      // guaranteed co-resident

    fused_kernel<<<nblk, TPB>>>(xyz, scaling, rot, feat, opac, out, nblk);
}

// round 9
// speedup vs baseline: 1.1866x; 1.1633x over previous
#include <cuda_runtime.h>
#include <math.h>

#define NG   5000
#define IMH  512
#define IMW  512
#define HW   (IMH * IMW)
#define TPB  544                 // 17 warps/block
#define WPB  (TPB / 32)
#define ALPHA_T (1.0f / 255.0f)

// Interleaved RGBA accumulation scratch (16B/pixel -> one v4 red per splat).
// Zero-initialized at module load; phase 2 re-zeroes every call, so
// "scratch == 0 on entry" is an invariant of kernel_launch.
__device__ float4 g_scratch4[HW];

// Sense-reversing grid barrier state (re-entrant across graph replays).
__device__ unsigned          g_cnt   = 0;
__device__ volatile unsigned g_sense = 0;

__device__ __forceinline__ void grid_barrier(int nblk) {
    __syncthreads();
    if (threadIdx.x == 0) {
        const unsigned my = g_sense;
        __threadfence();                       // publish this block's REDs
        const unsigned old = atomicAdd(&g_cnt, 1u);
        if (old == (unsigned)nblk - 1u) {
            g_cnt = 0;
            atomicExch((unsigned*)&g_sense, my + 1u);   // release
        } else {
            unsigned ns = 32;
            while (g_sense == my) { __nanosleep(ns); if (ns < 256) ns += ns; }
        }
    }
    __syncthreads();
}

// fast tanh via __expf: tanh(x) = sgn(x) * (1 - 2/(1 + e^{2|x|}))
__device__ __forceinline__ float fast_tanh(float x) {
    const float ax = fabsf(x);
    const float e  = __expf(2.0f * ax);
    const float t  = 1.0f - 2.0f / (1.0f + e);
    return copysignf(t, x);
}

__device__ __forceinline__ void red_add_v4(float4* addr, float r, float g,
                                           float b) {
    asm volatile("red.global.add.v4.f32 [%0], {%1, %2, %3, %4};"
                 :: "l"(addr), "f"(r), "f"(g), "f"(b), "f"(0.0f)
                 : "memory");
}

__global__ void __launch_bounds__(TPB, 2)      // 2 blocks/SM co-resident
fused_kernel(const float* __restrict__ xyz,
             const float* __restrict__ scaling,
             const float* __restrict__ rot,
             const float* __restrict__ feat,
             const float* __restrict__ opac,
             float* __restrict__ out,
             int nblk) {
    const int lane  = threadIdx.x & 31;
    const int warp  = blockIdx.x * WPB + (threadIdx.x >> 5);
    const int nwarp = nblk * WPB;

    // ---------------- phase 1: splat gaussians into g_scratch4 ---------------
    for (int g = warp; g < NG; g += nwarp) {
        const float mx = fast_tanh(__ldg(&xyz[2 * g + 0]));
        const float my = fast_tanh(__ldg(&xyz[2 * g + 1]));
        const float sx = fabsf(__ldg(&scaling[2 * g + 0]) + 0.5f);
        const float sy = fabsf(__ldg(&scaling[2 * g + 1]) + 0.5f);
        const float theta = (1.0f / (1.0f + __expf(-__ldg(&rot[g]))))
                            * 6.283185307179586f;

        const float cx = 0.5f * ((mx + 1.0f) * (float)IMW - 1.0f);
        const float cy = 0.5f * ((my + 1.0f) * (float)IMH - 1.0f);

        const float sth = __sinf(theta);
        const float cth = __cosf(theta);
        const float sx2 = sx * sx;
        const float sy2 = sy * sy;
        const float a = cth * cth * sx2 + sth * sth * sy2;   // Sigma_xx
        const float b = cth * sth * (sx2 - sy2);             // Sigma_xy
        const float c = sth * sth * sx2 + cth * cth * sy2;   // Sigma_yy
        const float det = a * c - b * b;
        if (!(det > 0.0f)) continue;
        const float inv_det = __fdividef(1.0f, fmaxf(det, 1e-12f));
        const float A =  c * inv_det;
        const float B = -b * inv_det;
        const float C =  a * inv_det;

        const float op = __ldg(&opac[g]);
        if (!(op > ALPHA_T)) continue;
        const float smax = __logf(255.0f * op);  // alpha>1/255 <=> sigma<smax
        if (!(smax > 0.0f)) continue;

        // exact AABB of the iso-ellipse sigma == smax
        const float dxm = sqrtf(2.0f * smax * a);
        const float dym = sqrtf(2.0f * smax * c);

        const int x0 = max(0,       (int)ceilf (cx - dxm));
        const int x1 = min(IMW - 1, (int)floorf(cx + dxm));
        const int y0 = max(0,       (int)ceilf (cy - dym));
        const int y1 = min(IMH - 1, (int)floorf(cy + dym));
        if (x0 > x1 || y0 > y1) continue;

        // pow2-rounded width -> mask/shift pixel indexing (no div/mod)
        const int w  = x1 - x0 + 1;
        const int sh = (w <= 1) ? 0 : (32 - __clz(w - 1));
        const int mask  = (1 << sh) - 1;
        const int total = (y1 - y0 + 1) << sh;

        const float cr = __ldg(&feat[3 * g + 0]);
        const float cg = __ldg(&feat[3 * g + 1]);
        const float cb = __ldg(&feat[3 * g + 2]);

        for (int i = lane; i < total; i += 32) {
            const int px = x0 + (i & mask);
            if (px > x1) continue;                      // pow2 padding reject
            const int py = y0 + (i >> sh);
            const float dx = cx - (float)px;
            const float dy = cy - (float)py;
            const float sigma = 0.5f * (A * dx * dx + C * dy * dy)
                                + B * dx * dy;
            if (sigma >= 0.0f && sigma < smax) {        // == alpha > 1/255
                const float alpha = op * __expf(-sigma);
                red_add_v4(&g_scratch4[py * IMW + px],
                           alpha * cr, alpha * cg, alpha * cb);
            }
        }
    }

    grid_barrier(nblk);

    // ---- phase 2: gather RGBA -> planar out, re-zero scratch for next call --
    const int nthr = nblk * TPB;
    const float4 z = make_float4(0.f, 0.f, 0.f, 0.f);
    for (int p = blockIdx.x * TPB + threadIdx.x; p < HW; p += nthr) {
        float4 v = __ldcg(&g_scratch4[p]);
        __stcg(&out[p],          fminf(fmaxf(v.x, 0.f), 1.f));
        __stcg(&out[HW + p],     fminf(fmaxf(v.y, 0.f), 1.f));
        __stcg(&out[2 * HW + p], fminf(fmaxf(v.z, 0.f), 1.f));
        __stcg((float4*)&g_scratch4[p], z);             // restore zero invariant
    }
}

// ---------------------------------------------------------------------------
// Inputs (metadata order): _xyz(N,2) _scaling(N,2) _rotation(N,1)
//                          _features_dc(N,3) _opacity(N,1)
// Output: float32 (1,3,512,512)
// ---------------------------------------------------------------------------
extern "C" void kernel_launch(void* const* d_in, const int* in_sizes, int n_in,
                              void* d_out, int out_size) {
    const float* xyz     = (const float*)d_in[0];
    const float* scaling = (const float*)d_in[1];
    const float* rot     = (const float*)d_in[2];
    const float* feat    = (const float*)d_in[3];
    const float* opac    = (const float*)d_in[4];
    float* out = (float*)d_out;

    int dev = 0, sms = 152;
    cudaGetDevice(&dev);
    cudaDeviceGetAttribute(&sms, cudaDevAttrMultiProcessorCount, dev);
    const int nblk = sms * 2;                      // all co-resident, one wave

    fused_kernel<<<nblk, TPB>>>(xyz, scaling, rot, feat, opac, out, nblk);
}